// round 10
// baseline (speedup 1.0000x reference)
#include <cuda_runtime.h>
#include <cuda_fp16.h>
#include <cstdint>
#include <math.h>

#define TB 64
#define TT 2048
#define TC 96
#define TS 256
#define NEGF (-1e30f)
#define LOG2E 1.4426950408889634f
#define LN2   0.6931471805599453f
#define NTH 256            // 8 warps; thread i owns states 2i, 2i+1; t255 also 512

// G[b][t][j] = log2 p(lab_j | t)  (fp16);  gB[b][t] = log2 p(blank | t)
__device__ __align__(16) __half g_glab[(size_t)TB * TT * TS];
__device__ __align__(16) __half g_gblank[(size_t)TB * TT];

__device__ __forceinline__ float ex2f_(float x) {
    float r; asm("ex2.approx.f32 %0, %1;" : "=f"(r) : "f"(x)); return r;
}
__device__ __forceinline__ float lg2f_(float x) {
    float r; asm("lg2.approx.f32 %0, %1;" : "=f"(r) : "f"(x)); return r;
}
__device__ __forceinline__ float lse2f_(float a, float b) {
    float m = fmaxf(a, b), n = fminf(a, b);
    return m + lg2f_(1.0f + ex2f_(n - m));
}
__device__ __forceinline__ float lse3f_(float a, float b, float c) {
    float s1 = fmaxf(a, b), t1 = fminf(a, b);
    float m  = fmaxf(s1, c);
    float md = fmaxf(fminf(s1, c), t1);
    float mn = fminf(t1, c);
    return m + lg2f_(1.0f + ex2f_(md - m) + ex2f_(mn - m));
}

// ---------------------------------------------------------------------------
// Gather: precise log-softmax + class gather -> fp16 log2-probs.
// 256 threads = 8 warps, one warp per t-row; grid (TT/8, TB).
// ---------------------------------------------------------------------------
__global__ void __launch_bounds__(256) gather_kernel(
    const float* __restrict__ x, const int* __restrict__ tgt32, float* out)
{
    __shared__ int   lab[TS];
    __shared__ float raw[8][TC];

    const int tid = threadIdx.x, lane = tid & 31, r = tid >> 5;
    const int b = blockIdx.y, t0 = blockIdx.x * 8;

    if (b == 0 && blockIdx.x == 0 && tid == 0) *out = 0.0f;

    const bool is64 = (tgt32[1] == 0);          // labels>=1 => hi word 0 iff i64 LE
    const int  stride = is64 ? 2 : 1;
    lab[tid] = tgt32[((size_t)b * TS + tid) * stride];

    const float* xr = x + ((size_t)b * TT + t0 + r) * TC;
    float v0 = xr[lane], v1 = xr[lane + 32], v2 = xr[lane + 64];
    raw[r][lane] = v0; raw[r][lane + 32] = v1; raw[r][lane + 64] = v2;
    float m = fmaxf(fmaxf(v0, v1), v2);
    #pragma unroll
    for (int o = 16; o; o >>= 1) m = fmaxf(m, __shfl_xor_sync(0xffffffffu, m, o));
    float s = expf(v0 - m) + expf(v1 - m) + expf(v2 - m);   // precise
    #pragma unroll
    for (int o = 16; o; o >>= 1) s += __shfl_xor_sync(0xffffffffu, s, o);
    float lse2 = fmaf(m, LOG2E, log2f(s));                  // precise
    __syncthreads();

    __half* Gr = g_glab + (((size_t)b * TT + t0 + r) << 8);
    #pragma unroll
    for (int j = lane; j < TS; j += 32)
        Gr[j] = __float2half(fmaf(raw[r][lab[j]], LOG2E, -lse2));
    if (lane == 0)
        g_gblank[(size_t)b * TT + t0 + r] =
            __float2half(fmaf(raw[r][0], LOG2E, -lse2));
}

// ---------------------------------------------------------------------------
// Main kernel: one CTA per batch; 8 warps; register-prefetched fp16 probs.
// ---------------------------------------------------------------------------
__global__ void __launch_bounds__(NTH, 1) ctc_kernel(
    const int* __restrict__ tgt32,
    const int* __restrict__ tmask,
    float*     __restrict__ out)
{
    __shared__ float shOB[2][8];       // [parity][warp] boundary odd alpha
    __shared__ float fin[514];
    __shared__ int   tlen_sh;

    const int tid = threadIdx.x, lane = tid & 31, w = tid >> 5;
    const int b = blockIdx.x, i = tid;

    const bool is64 = (tgt32[1] == 0);
    const int  stride = is64 ? 2 : 1;
    const int* trow = tgt32 + (size_t)b * TS * stride;
    const int  myLab   = trow[i * stride];
    const int  leftLab = (i > 0) ? trow[(i - 1) * stride] : -1;
    const bool skip    = (i > 0) && (myLab != leftLab);

    if (tid < 16) ((float*)shOB)[tid] = NEGF;
    if (w == 0) {
        int s = 0;
        #pragma unroll
        for (int k = lane; k < TS; k += 32) s += tmask[b * TS + k];
        #pragma unroll
        for (int o = 16; o; o >>= 1) s += __shfl_xor_sync(0xffffffffu, s, o);
        if (lane == 0) tlen_sh = s;
    }
    __syncthreads();

    const __half* GL = g_glab   + ((size_t)b * TT << 8);
    const __half* GB = g_gblank + (size_t)b * TT;

    // 8-deep register prefetch of this thread's label log-probs
    __half pf[8];
    #pragma unroll
    for (int k = 0; k < 8; ++k) pf[k] = __ldg(GL + (k << 8) + i);
    uint4 blv = *(const uint4*)(GB);           // blanks t=0..7 (uniform)

    // alphas: aE = alpha[2i], aO = alpha[2i+1], aX = alpha[512] (thread 255)
    // seed "virtual t=-1": aE(0)=0 makes the uniform update emit alpha0 at t=0
    float aE = (i == 0) ? 0.0f : NEGF;
    float aO = NEGF, aX = NEGF;

    for (int tb = 0; tb < TT; tb += 8) {
        uint4 bln = blv;
        if (tb + 8 < TT) bln = *(const uint4*)(GB + tb + 8);
        const __half* bl8 = (const __half*)&blv;
        #pragma unroll
        for (int k = 0; k < 8; ++k) {
            const int t = tb + k;
            __syncthreads();
            float lp  = __half2float(pf[k]);
            float lpB = __half2float(bl8[k]);
            if (tb + 8 < TT) pf[k] = __ldg(GL + ((size_t)(t + 8) << 8) + i);

            float lo = __shfl_up_sync(0xffffffffu, aO, 1);   // alpha[2i-1] old
            if (lane == 0) lo = w ? shOB[t & 1][w - 1] : NEGF;

            float nE = lse2f_(aE, lo) + lpB;                 // state 2i
            float nO = lse3f_(aO, aE, skip ? lo : NEGF) + lp;// state 2i+1
            if (i == NTH - 1) aX = lse2f_(aX, aO) + lpB;     // state 512
            aE = nE; aO = nO;

            if (lane == 31) shOB[(t + 1) & 1][w] = aO;
        }
        blv = bln;
    }

    fin[2 * i] = aE;
    fin[2 * i + 1] = aO;
    if (i == NTH - 1) fin[512] = aX;
    __syncthreads();

    if (tid == 0) {
        int len = tlen_sh;
        float loss = 0.0f;
        if (len >= 1 && len <= TS) {
            float la = lse2f_(fin[2 * len], fin[2 * len - 1]);
            float l  = -la * LN2;
            if (isfinite(l) && l < 1e29f)
                loss = l / ((float)len * (float)TB);
        }
        atomicAdd(out, loss);
    }
}

// ---------------------------------------------------------------------------
extern "C" void kernel_launch(void* const* d_in, const int* in_sizes, int n_in,
                              void* d_out, int out_size) {
    const float* x     = (const float*)d_in[0];   // predictions [B,T,C] f32
    const int*   tgt   = (const int*)  d_in[1];   // targets (int32 or int64 words)
    const int*   tmask = (const int*)  d_in[3];   // targets_mask [B,S] i32
    float* out = (float*)d_out;

    dim3 ggrid(TT / 8, TB);
    gather_kernel<<<ggrid, 256>>>(x, tgt, out);
    ctc_kernel<<<TB, NTH>>>(tgt, tmask, out);
}

// round 11
// speedup vs baseline: 1.0927x; 1.0927x over previous
#include <cuda_runtime.h>
#include <cstdint>
#include <math.h>

#define TB 64
#define TT 2048
#define TC 96
#define TS 256
#define NEGF (-1e30f)
#define LOG2E 1.4426950408889634f
#define LN2   0.6931471805599453f

#define NTH 288            // 9 warps; threads 0..255 own states 2i,2i+1; 256 owns 512
#define RCH 5              // ring chunks of 8 rows (5*8*100*4 = 16000 B)
#define NCHK (TT / 8)

// log-softmax denominators, log2 domain
__device__ float g_lse[TB * TT];

__device__ __forceinline__ float ex2f_(float x) {
    float r; asm("ex2.approx.f32 %0, %1;" : "=f"(r) : "f"(x)); return r;
}
__device__ __forceinline__ float lg2f_(float x) {
    float r; asm("lg2.approx.f32 %0, %1;" : "=f"(r) : "f"(x)); return r;
}
__device__ __forceinline__ float lse2f_(float a, float b) {
    float m = fmaxf(a, b), n = fminf(a, b);
    return m + lg2f_(1.0f + ex2f_(n - m));
}
__device__ __forceinline__ float lse3f_(float a, float b, float c) {
    float s1 = fmaxf(a, b), t1 = fminf(a, b);
    float m  = fmaxf(s1, c);
    float md = fmaxf(fminf(s1, c), t1);
    float mn = fminf(t1, c);
    return m + lg2f_(1.0f + ex2f_(md - m) + ex2f_(mn - m));
}

// ---------------------------------------------------------------------------
__global__ void lse_kernel(const float* __restrict__ x, float* out) {
    int row = blockIdx.x * 4 + (threadIdx.x >> 5);
    if (blockIdx.x == 0 && threadIdx.x == 0) *out = 0.0f;
    if (row >= TB * TT) return;
    int lane = threadIdx.x & 31;
    const float* p = x + (size_t)row * TC;
    float v0 = p[lane], v1 = p[lane + 32], v2 = p[lane + 64];
    float m = fmaxf(fmaxf(v0, v1), v2);
    #pragma unroll
    for (int o = 16; o; o >>= 1) m = fmaxf(m, __shfl_xor_sync(0xffffffffu, m, o));
    float s = expf(v0 - m) + expf(v1 - m) + expf(v2 - m);
    #pragma unroll
    for (int o = 16; o; o >>= 1) s += __shfl_xor_sync(0xffffffffu, s, o);
    if (lane == 0) g_lse[row] = fmaf(m, LOG2E, log2f(s));
}

// ---------------------------------------------------------------------------
// Main kernel: one CTA per batch; 2-step trapezoid rounds (1 barrier / 2 t).
// ---------------------------------------------------------------------------
__global__ void __launch_bounds__(NTH, 1) ctc_kernel(
    const float* __restrict__ x,
    const int*   __restrict__ tgt32,
    const int*   __restrict__ tmask,
    float*       __restrict__ out)
{
    __shared__ __align__(16) float ring[RCH][8 * 100];  // 8 rows: 96 logits + lse
    __shared__ float shOB[2][8][4];    // [parity][warp 0..7][aO31, aE31, aO30, pad]
    __shared__ float fin[514];
    __shared__ int   lab[TS];
    __shared__ int   tlen_sh;

    const int tid = threadIdx.x, lane = tid & 31, w = tid >> 5;
    const int b = blockIdx.x, i = tid;

    const bool is64 = (tgt32[1] == 0);   // labels>=1 => hi word 0 iff i64 LE
    const int  stride = is64 ? 2 : 1;
    if (tid < TS) lab[tid] = tgt32[((size_t)b * TS + tid) * stride];
    if (tid < 64) ((float*)shOB)[tid] = NEGF;
    if (w == 0) {
        int s = 0;
        #pragma unroll
        for (int k = lane; k < TS; k += 32) s += tmask[b * TS + k];
        #pragma unroll
        for (int o = 16; o; o >>= 1) s += __shfl_xor_sync(0xffffffffu, s, o);
        if (lane == 0) tlen_sh = s;
    }
    __syncthreads();

    // per-thread trellis config
    int  cls = 0, clsL = 0;
    bool sk = false, skL = false;
    if (i < 256) {
        cls = lab[i];
        if (i > 0) { clsL = lab[i - 1]; sk = (cls != clsL); }
        if (i > 1) skL = (lab[i - 1] != lab[i - 2]);
        else if (i == 1) skL = false;
    } else if (i == 256) {               // ghost = state 511 (label lab[255])
        clsL = lab[255];
        skL  = (lab[255] != lab[254]);
    }

    const float* xb   = x + (size_t)b * TT * TC;
    const float* lseb = g_lse + (size_t)b * TT;

    // one chunk = 8 rows; logits contiguous in gmem (768 floats)
    auto issue_chunk = [&](int c) {
        if (c < NCHK) {
            unsigned sa = (unsigned)__cvta_generic_to_shared(ring[c % RCH]);
            const float* src = xb + (size_t)c * 768;
            if (tid < 192) {
                int row = tid / 24, word = tid % 24;
                asm volatile("cp.async.ca.shared.global [%0], [%1], 16;"
                             :: "r"(sa + (row * 100 + word * 4) * 4),
                                "l"(src + row * 96 + word * 4));
            } else if (tid < 200) {
                int row = tid - 192;
                asm volatile("cp.async.ca.shared.global [%0], [%1], 4;"
                             :: "r"(sa + (row * 100 + 96) * 4),
                                "l"(lseb + c * 8 + row));
            }
        }
        asm volatile("cp.async.commit_group;");
    };

    issue_chunk(0); issue_chunk(1); issue_chunk(2); issue_chunk(3);

    // virtual t=-1 seed: aE(i=0)=0 makes the uniform round emit alpha0 at t=0
    float aE = (i == 0) ? 0.0f : NEGF;
    float aO = NEGF;
    int   pb = 0;

    for (int r = 0; r < TT / 2; ++r) {
        const int t1 = 2 * r;
        if ((t1 & 7) == 0) asm volatile("cp.async.wait_group 3;");
        __syncthreads();
        if ((t1 & 7) == 0) issue_chunk((t1 >> 3) + 4);

        const float* R1 = ring[(t1 >> 3) % RCH] + (t1 & 7) * 100;
        const float* R2 = R1 + 100;                 // t1+1, same chunk

        // left-neighbor alphas at round start
        float aO_L  = __shfl_up_sync(0xffffffffu, aO, 1);
        float aE_L  = __shfl_up_sync(0xffffffffu, aE, 1);
        float aO_LL = __shfl_up_sync(0xffffffffu, aO, 2);
        if (lane == 0) {
            if (w) { aO_L = shOB[pb][w-1][0]; aE_L = shOB[pb][w-1][1]; aO_LL = shOB[pb][w-1][2]; }
            else   { aO_L = NEGF; aE_L = NEGF; aO_LL = NEGF; }
        } else if (lane == 1) {
            aO_LL = w ? shOB[pb][w-1][0] : NEGF;
        }

        float lse1 = R1[96], lse2v = R2[96];
        float lpB1 = fmaf(R1[0], LOG2E, -lse1);
        float lpB2 = fmaf(R2[0], LOG2E, -lse2v);

        if (i < 256) {
            float lp1  = fmaf(R1[cls],  LOG2E, -lse1);
            float lpL1 = fmaf(R1[clsL], LOG2E, -lse1);
            float lp2  = fmaf(R2[cls],  LOG2E, -lse2v);
            // step 1 (row t1)
            float g  = lse3f_(aO_L, aE_L, skL ? aO_LL : NEGF) + lpL1;  // ghost 2i-1
            float nE = lse2f_(aE, aO_L) + lpB1;                        // state 2i
            float nO = lse3f_(aO, aE, sk ? aO_L : NEGF) + lp1;         // state 2i+1
            // step 2 (row t1+1)
            aE = lse2f_(nE, g) + lpB2;
            aO = lse3f_(nO, nE, sk ? g : NEGF) + lp2;
        } else if (i == 256) {                                         // state 512
            float lpL1 = fmaf(R1[clsL], LOG2E, -lse1);
            float g  = lse3f_(aO_L, aE_L, skL ? aO_LL : NEGF) + lpL1;  // ghost 511
            float a1 = lse2f_(aE, aO_L) + lpB1;
            aE = lse2f_(a1, g) + lpB2;
        }

        if (w < 8) {
            if (lane == 31) { shOB[pb ^ 1][w][0] = aO; shOB[pb ^ 1][w][1] = aE; }
            else if (lane == 30) shOB[pb ^ 1][w][2] = aO;
        }
        pb ^= 1;
    }

    if (i < 256) { fin[2 * i] = aE; fin[2 * i + 1] = aO; }
    if (i == 256) fin[512] = aE;
    __syncthreads();

    if (tid == 0) {
        int len = tlen_sh;
        float loss = 0.0f;
        if (len >= 1 && len <= TS) {
            float la = lse2f_(fin[2 * len], fin[2 * len - 1]);
            float l  = -la * LN2;
            if (isfinite(l) && l < 1e29f)
                loss = l / ((float)len * (float)TB);
        }
        atomicAdd(out, loss);
    }
}

// ---------------------------------------------------------------------------
extern "C" void kernel_launch(void* const* d_in, const int* in_sizes, int n_in,
                              void* d_out, int out_size) {
    const float* x     = (const float*)d_in[0];   // predictions [B,T,C] f32
    const int*   tgt   = (const int*)  d_in[1];   // targets (int32 or int64 words)
    const int*   tmask = (const int*)  d_in[3];   // targets_mask [B,S] i32
    float* out = (float*)d_out;

    lse_kernel<<<(TB * TT + 3) / 4, 128>>>(x, out);
    ctc_kernel<<<TB, NTH>>>(x, tgt, tmask, out);
}

// round 12
// speedup vs baseline: 1.6438x; 1.5043x over previous
#include <cuda_runtime.h>
#include <cuda_fp16.h>
#include <cstdint>
#include <math.h>

#define TB 64
#define TT 2048
#define TC 96
#define TS 256
#define NEGF (-1e30f)
#define LOG2E 1.4426950408889634f
#define LN2   0.6931471805599453f

#define NTH 288            // 9 warps; threads 0..255: states 2i,2i+1; 256: state 512
#define GROW 264           // halves per gathered row (258 used; 528 B, 16B-aligned)
#define RCH 5              // ring chunks of 8 rows
#define NCHK (TT / 8)

// G[b][t][i] = log2 p(lab_i | t) fp16, [256] = blank, rest pad
__device__ __align__(16) __half g_gt[(size_t)TB * TT * GROW];

__device__ __forceinline__ float ex2f_(float x) {
    float r; asm("ex2.approx.f32 %0, %1;" : "=f"(r) : "f"(x)); return r;
}
__device__ __forceinline__ float lg2f_(float x) {
    float r; asm("lg2.approx.f32 %0, %1;" : "=f"(r) : "f"(x)); return r;
}
__device__ __forceinline__ float lse2f_(float a, float b) {
    float m = fmaxf(a, b), n = fminf(a, b);
    return m + lg2f_(1.0f + ex2f_(n - m));
}
__device__ __forceinline__ float lse3f_(float a, float b, float c) {
    float s1 = fmaxf(a, b), t1 = fminf(a, b);
    float m  = fmaxf(s1, c);
    float md = fmaxf(fminf(s1, c), t1);
    float mn = fminf(t1, c);
    return m + lg2f_(1.0f + ex2f_(md - m) + ex2f_(mn - m));
}

// ---------------------------------------------------------------------------
// Gather: precise log-softmax + class gather -> fp16 log2-prob table.
// 256 threads = 8 warps, one warp per t-row; grid (TT/8, TB).
// ---------------------------------------------------------------------------
__global__ void __launch_bounds__(256) gather_kernel(
    const float* __restrict__ x, const int* __restrict__ tgt32, float* out)
{
    __shared__ int   lab[TS];
    __shared__ float raw[8][TC];

    const int tid = threadIdx.x, lane = tid & 31, r = tid >> 5;
    const int b = blockIdx.y, t0 = blockIdx.x * 8;

    if (b == 0 && blockIdx.x == 0 && tid == 0) *out = 0.0f;

    const bool is64 = (tgt32[1] == 0);       // labels>=1 => hi word 0 iff i64 LE
    const int  stride = is64 ? 2 : 1;
    lab[tid] = tgt32[((size_t)b * TS + tid) * stride];

    const float* xr = x + ((size_t)b * TT + t0 + r) * TC;
    float v0 = xr[lane], v1 = xr[lane + 32], v2 = xr[lane + 64];
    raw[r][lane] = v0; raw[r][lane + 32] = v1; raw[r][lane + 64] = v2;
    float m = fmaxf(fmaxf(v0, v1), v2);
    #pragma unroll
    for (int o = 16; o; o >>= 1) m = fmaxf(m, __shfl_xor_sync(0xffffffffu, m, o));
    float s = expf(v0 - m) + expf(v1 - m) + expf(v2 - m);   // precise
    #pragma unroll
    for (int o = 16; o; o >>= 1) s += __shfl_xor_sync(0xffffffffu, s, o);
    float lse2 = fmaf(m, LOG2E, log2f(s));                  // precise
    __syncthreads();

    __half* Gr = g_gt + ((size_t)b * TT + t0 + r) * GROW;
    #pragma unroll
    for (int j = lane; j < TS; j += 32)
        Gr[j] = __float2half(fmaf(raw[r][lab[j]], LOG2E, -lse2));
    if (lane == 0)
        Gr[256] = __float2half(fmaf(raw[r][0], LOG2E, -lse2));
}

// ---------------------------------------------------------------------------
// Main kernel: one CTA per batch; per-step barrier; lean fp16-fed body.
// ---------------------------------------------------------------------------
__global__ void __launch_bounds__(NTH, 1) ctc_kernel(
    const int* __restrict__ tgt32,
    const int* __restrict__ tmask,
    float*     __restrict__ out)
{
    __shared__ __align__(16) __half ring[RCH][8 * GROW];   // 5*8*528 B = 21120 B
    __shared__ float shOB[2][8];       // [parity][warp] boundary odd alpha
    __shared__ float fin[514];
    __shared__ int   lab[TS];
    __shared__ int   tlen_sh;

    const int tid = threadIdx.x, lane = tid & 31, w = tid >> 5;
    const int b = blockIdx.x, i = tid;

    const bool is64 = (tgt32[1] == 0);
    const int  stride = is64 ? 2 : 1;
    if (tid < TS) lab[tid] = tgt32[((size_t)b * TS + tid) * stride];
    if (tid < 16) ((float*)shOB)[tid] = NEGF;
    if (w == 0) {
        int s = 0;
        #pragma unroll
        for (int k = lane; k < TS; k += 32) s += tmask[b * TS + k];
        #pragma unroll
        for (int o = 16; o; o >>= 1) s += __shfl_xor_sync(0xffffffffu, s, o);
        if (lane == 0) tlen_sh = s;
    }
    __syncthreads();

    const bool mid  = (i < 256);
    const bool skip = mid && (i > 0) && (lab[i] != lab[i - 1]);

    const __half* Gb = g_gt + ((size_t)b * TT) * GROW;

    // one chunk = 8 rows = 264*16 B contiguous; one cp.async per thread
    auto issue_chunk = [&](int c) {
        if (c < NCHK) {
            unsigned sa = (unsigned)__cvta_generic_to_shared(ring[c % RCH]);
            const __half* src = Gb + (size_t)c * (8 * GROW);
            if (tid < 264)
                asm volatile("cp.async.ca.shared.global [%0], [%1], 16;"
                             :: "r"(sa + tid * 16), "l"(src + tid * 8));
        }
        asm volatile("cp.async.commit_group;");
    };

    issue_chunk(0); issue_chunk(1); issue_chunk(2); issue_chunk(3);

    // virtual t=-1 seed: aE(i=0)=0 makes the uniform loop emit alpha0 at t=0
    float aE = (i == 0) ? 0.0f : NEGF;
    float aO = NEGF;

    for (int tb = 0; tb < TT; tb += 8) {
        asm volatile("cp.async.wait_group 3;");     // chunk tb/8 complete
        __syncthreads();                            // barrier for step tb
        issue_chunk((tb >> 3) + 4);

        const __half* Rc = ring[(tb >> 3) % RCH];
        #pragma unroll
        for (int k = 0; k < 8; ++k) {
            const int t = tb + k;
            if (k) __syncthreads();
            const __half* R = Rc + k * GROW;

            float lp  = __half2float(R[mid ? i : 256]);
            float lpB = __half2float(R[256]);

            float lo = __shfl_up_sync(0xffffffffu, aO, 1);   // alpha[2i-1] old
            if (lane == 0) lo = w ? shOB[t & 1][w - 1] : NEGF;

            if (mid) {
                float nE = lse2f_(aE, lo) + lpB;                  // state 2i
                float nO = lse3f_(aO, aE, skip ? lo : NEGF) + lp; // state 2i+1
                aE = nE; aO = nO;
                if (lane == 31) shOB[(t + 1) & 1][w] = aO;
            } else if (i == 256) {
                aE = lse2f_(aE, lo) + lpB;                        // state 512
            }
        }
    }

    if (mid) { fin[2 * i] = aE; fin[2 * i + 1] = aO; }
    if (i == 256) fin[512] = aE;
    __syncthreads();

    if (tid == 0) {
        int len = tlen_sh;
        float loss = 0.0f;
        if (len >= 1 && len <= TS) {
            float la = lse2f_(fin[2 * len], fin[2 * len - 1]);
            float l  = -la * LN2;
            if (isfinite(l) && l < 1e29f)
                loss = l / ((float)len * (float)TB);
        }
        atomicAdd(out, loss);
    }
}

// ---------------------------------------------------------------------------
extern "C" void kernel_launch(void* const* d_in, const int* in_sizes, int n_in,
                              void* d_out, int out_size) {
    const float* x     = (const float*)d_in[0];   // predictions [B,T,C] f32
    const int*   tgt   = (const int*)  d_in[1];   // targets (int32 or int64 words)
    const int*   tmask = (const int*)  d_in[3];   // targets_mask [B,S] i32
    float* out = (float*)d_out;

    dim3 ggrid(TT / 8, TB);
    gather_kernel<<<ggrid, 256>>>(x, tgt, out);
    ctc_kernel<<<TB, NTH>>>(tgt, tmask, out);
}

// round 13
// speedup vs baseline: 1.8103x; 1.1013x over previous
#include <cuda_runtime.h>
#include <cuda_fp16.h>
#include <cstdint>
#include <math.h>

#define TB 64
#define TT 2048
#define TC 96
#define TS 256
#define NEGF (-1e30f)
#define LOG2E 1.4426950408889634f
#define LN2   0.6931471805599453f

#define NTH 320            // 10 warps; warp w: threads 0..3 ghost, 4..31 own 28 pairs
#define NW  10
#define GROW 264           // halves per gathered row (258 used; 528 B)
#define RCH 5              // ring chunks of 8 rows
#define NCHK (TT / 8)

// G[b][t][i] = log2 p(lab_i | t) fp16, [256] = blank
__device__ __align__(16) __half g_gt[(size_t)TB * TT * GROW];

__device__ __forceinline__ float ex2f_(float x) {
    float r; asm("ex2.approx.f32 %0, %1;" : "=f"(r) : "f"(x)); return r;
}
__device__ __forceinline__ float lg2f_(float x) {
    float r; asm("lg2.approx.f32 %0, %1;" : "=f"(r) : "f"(x)); return r;
}
__device__ __forceinline__ float lse2f_(float a, float b) {
    float m = fmaxf(a, b), n = fminf(a, b);
    return m + lg2f_(1.0f + ex2f_(n - m));
}
__device__ __forceinline__ float lse3f_(float a, float b, float c) {
    float s1 = fmaxf(a, b), t1 = fminf(a, b);
    float m  = fmaxf(s1, c);
    float md = fmaxf(fminf(s1, c), t1);
    float mn = fminf(t1, c);
    return m + lg2f_(1.0f + ex2f_(md - m) + ex2f_(mn - m));
}

// ---------------------------------------------------------------------------
// Gather: precise log-softmax + class gather -> fp16 log2-prob table.
// ---------------------------------------------------------------------------
__global__ void __launch_bounds__(256) gather_kernel(
    const float* __restrict__ x, const int* __restrict__ tgt32, float* out)
{
    __shared__ int   lab[TS];
    __shared__ float raw[8][TC];

    const int tid = threadIdx.x, lane = tid & 31, r = tid >> 5;
    const int b = blockIdx.y, t0 = blockIdx.x * 8;

    if (b == 0 && blockIdx.x == 0 && tid == 0) *out = 0.0f;

    const bool is64 = (tgt32[1] == 0);       // labels>=1 => hi word 0 iff i64 LE
    const int  stride = is64 ? 2 : 1;
    lab[tid] = tgt32[((size_t)b * TS + tid) * stride];

    const float* xr = x + ((size_t)b * TT + t0 + r) * TC;
    float v0 = xr[lane], v1 = xr[lane + 32], v2 = xr[lane + 64];
    raw[r][lane] = v0; raw[r][lane + 32] = v1; raw[r][lane + 64] = v2;
    float m = fmaxf(fmaxf(v0, v1), v2);
    #pragma unroll
    for (int o = 16; o; o >>= 1) m = fmaxf(m, __shfl_xor_sync(0xffffffffu, m, o));
    float s = expf(v0 - m) + expf(v1 - m) + expf(v2 - m);
    #pragma unroll
    for (int o = 16; o; o >>= 1) s += __shfl_xor_sync(0xffffffffu, s, o);
    float lse2 = fmaf(m, LOG2E, log2f(s));
    __syncthreads();

    __half* Gr = g_gt + ((size_t)b * TT + t0 + r) * GROW;
    #pragma unroll
    for (int j = lane; j < TS; j += 32)
        Gr[j] = __float2half(fmaf(raw[r][lab[j]], LOG2E, -lse2));
    if (lane == 0)
        Gr[256] = __float2half(fmaf(raw[r][0], LOG2E, -lse2));
}

// ---------------------------------------------------------------------------
// Main kernel: wavefront-blocked alpha recursion, 1 barrier per 4 timesteps.
// Warp w, thread j: pair p = 28w + j - 4 (states 2p, 2p+1). j<4 = ghost.
// ---------------------------------------------------------------------------
__global__ void __launch_bounds__(NTH, 1) ctc_kernel(
    const int* __restrict__ tgt32,
    const int* __restrict__ tmask,
    float*     __restrict__ out)
{
    __shared__ __align__(16) __half ring[RCH][8 * GROW];   // 21120 B
    __shared__ float bnd[2][NW][4][2];   // [parity][warp][slot][aE,aO]
    __shared__ float fin[514];
    __shared__ int   lab[TS];
    __shared__ int   tlen_sh;

    const int tid = threadIdx.x, lane = tid & 31, w = tid >> 5;
    const int b = blockIdx.x;
    const int p = 28 * w + lane - 4;     // pair index

    const bool is64 = (tgt32[1] == 0);
    const int  stride = is64 ? 2 : 1;
    if (tid < TS) lab[tid] = tgt32[((size_t)b * TS + tid) * stride];
    if (tid < 2 * NW * 4 * 2) ((float*)bnd)[tid] = NEGF;
    if (w == 0) {
        int s = 0;
        #pragma unroll
        for (int k = lane; k < TS; k += 32) s += tmask[b * TS + k];
        #pragma unroll
        for (int o = 16; o; o >>= 1) s += __shfl_xor_sync(0xffffffffu, s, o);
        if (lane == 0) tlen_sh = s;
    }
    __syncthreads();

    const bool hasLab = (p >= 0) && (p < 256);
    const bool skip   = hasLab && (p > 0) && (lab[p] != lab[p - 1]);

    const __half* Gb = g_gt + ((size_t)b * TT) * GROW;

    auto issue_chunk = [&](int c) {
        if (c < NCHK) {
            unsigned sa = (unsigned)__cvta_generic_to_shared(ring[c % RCH]);
            const __half* src = Gb + (size_t)c * (8 * GROW);
            if (tid < 264)
                asm volatile("cp.async.ca.shared.global [%0], [%1], 16;"
                             :: "r"(sa + tid * 16), "l"(src + tid * 8));
        }
        asm volatile("cp.async.commit_group;");
    };

    issue_chunk(0); issue_chunk(1); issue_chunk(2); issue_chunk(3);

    // virtual t=-1 seed: aE(p=0)=0 makes the uniform loop emit alpha0 at t=0
    float aE = (p == 0) ? 0.0f : NEGF;
    float aO = NEGF;
    int   pb = 0;

    for (int r = 0; r < TT / 4; ++r) {
        const int t0 = 4 * r;
        if ((r & 1) == 0) asm volatile("cp.async.wait_group 3;");
        __syncthreads();
        if ((r & 1) == 0) issue_chunk((r >> 1) + 4);

        // ghost refresh from left warp's last-round publish
        if (lane < 4 && w > 0) {
            aE = bnd[pb][w - 1][lane][0];
            aO = bnd[pb][w - 1][lane][1];
        }

        const __half* Rc = ring[(t0 >> 3) % RCH] + (t0 & 7) * GROW;
        float lpv[4], lpB[4];
        #pragma unroll
        for (int k = 0; k < 4; ++k) {
            const __half* R = Rc + k * GROW;
            lpv[k] = hasLab ? __half2float(R[p]) : NEGF;
            lpB[k] = __half2float(R[256]);
        }

        #pragma unroll
        for (int k = 0; k < 4; ++k) {
            float lo = __shfl_up_sync(0xffffffffu, aO, 1);
            if (lane == 0) lo = NEGF;
            float nE = lse2f_(aE, lo) + lpB[k];                   // state 2p
            float nO = lse3f_(aO, aE, skip ? lo : NEGF) + lpv[k]; // state 2p+1
            aE = nE; aO = nO;
        }

        if (lane >= 28) {            // publish top 4 owned pairs for warp w+1
            bnd[pb ^ 1][w][lane - 28][0] = aE;
            bnd[pb ^ 1][w][lane - 28][1] = aO;
        }
        pb ^= 1;
    }

    if (lane >= 4 && p >= 0 && p <= 256) {   // owned, in-trellis
        fin[2 * p] = aE;
        if (p < 256) fin[2 * p + 1] = aO;
    }
    __syncthreads();

    if (tid == 0) {
        int len = tlen_sh;
        float loss = 0.0f;
        if (len >= 1 && len <= TS) {
            float la = lse2f_(fin[2 * len], fin[2 * len - 1]);
            float l  = -la * LN2;
            if (isfinite(l) && l < 1e29f)
                loss = l / ((float)len * (float)TB);
        }
        atomicAdd(out, loss);
    }
}

// ---------------------------------------------------------------------------
extern "C" void kernel_launch(void* const* d_in, const int* in_sizes, int n_in,
                              void* d_out, int out_size) {
    const float* x     = (const float*)d_in[0];   // predictions [B,T,C] f32
    const int*   tgt   = (const int*)  d_in[1];   // targets (int32 or int64 words)
    const int*   tmask = (const int*)  d_in[3];   // targets_mask [B,S] i32
    float* out = (float*)d_out;

    dim3 ggrid(TT / 8, TB);
    gather_kernel<<<ggrid, 256>>>(x, tgt, out);
    ctc_kernel<<<TB, NTH>>>(tgt, tmask, out);
}

// round 14
// speedup vs baseline: 2.3194x; 1.2812x over previous
#include <cuda_runtime.h>
#include <cuda_fp16.h>
#include <cstdint>
#include <math.h>

#define TB 64
#define TT 2048
#define TC 96
#define TS 256
#define NEGF (-1e30f)
#define LOG2E 1.4426950408889634f
#define LN2   0.6931471805599453f

#define NW  11             // warps; warp w: lanes 0..7 ghost, lanes 8..31 own 24 pairs
#define NTH (NW * 32)      // 352
#define GH  8              // ghost lanes = trapezoid depth D
#define OWN 24             // owned pairs per warp
#define GROW 264           // halves per gathered row (258 used; 528 B)
#define RCH 5              // ring chunks of 8 rows
#define NCHK (TT / 8)

// G[b][t][i] = log2 p(lab_i | t) fp16, [256] = blank
__device__ __align__(16) __half g_gt[(size_t)TB * TT * GROW];

__device__ __forceinline__ float ex2f_(float x) {
    float r; asm("ex2.approx.f32 %0, %1;" : "=f"(r) : "f"(x)); return r;
}
__device__ __forceinline__ float lg2f_(float x) {
    float r; asm("lg2.approx.f32 %0, %1;" : "=f"(r) : "f"(x)); return r;
}
__device__ __forceinline__ float lse2f_(float a, float b) {
    float m = fmaxf(a, b), n = fminf(a, b);
    return m + lg2f_(1.0f + ex2f_(n - m));
}
__device__ __forceinline__ float lse3f_(float a, float b, float c) {
    float s1 = fmaxf(a, b), t1 = fminf(a, b);
    float m  = fmaxf(s1, c);
    float md = fmaxf(fminf(s1, c), t1);
    float mn = fminf(t1, c);
    return m + lg2f_(1.0f + ex2f_(md - m) + ex2f_(mn - m));
}

// ---------------------------------------------------------------------------
// Gather: precise log-softmax + class gather -> fp16 log2-prob table.
// ---------------------------------------------------------------------------
__global__ void __launch_bounds__(256) gather_kernel(
    const float* __restrict__ x, const int* __restrict__ tgt32, float* out)
{
    __shared__ int   lab[TS];
    __shared__ float raw[8][TC];

    const int tid = threadIdx.x, lane = tid & 31, r = tid >> 5;
    const int b = blockIdx.y, t0 = blockIdx.x * 8;

    if (b == 0 && blockIdx.x == 0 && tid == 0) *out = 0.0f;

    const bool is64 = (tgt32[1] == 0);       // labels>=1 => hi word 0 iff i64 LE
    const int  stride = is64 ? 2 : 1;
    lab[tid] = tgt32[((size_t)b * TS + tid) * stride];

    const float* xr = x + ((size_t)b * TT + t0 + r) * TC;
    float v0 = xr[lane], v1 = xr[lane + 32], v2 = xr[lane + 64];
    raw[r][lane] = v0; raw[r][lane + 32] = v1; raw[r][lane + 64] = v2;
    float m = fmaxf(fmaxf(v0, v1), v2);
    #pragma unroll
    for (int o = 16; o; o >>= 1) m = fmaxf(m, __shfl_xor_sync(0xffffffffu, m, o));
    float s = expf(v0 - m) + expf(v1 - m) + expf(v2 - m);
    #pragma unroll
    for (int o = 16; o; o >>= 1) s += __shfl_xor_sync(0xffffffffu, s, o);
    float lse2 = fmaf(m, LOG2E, log2f(s));
    __syncthreads();

    __half* Gr = g_gt + ((size_t)b * TT + t0 + r) * GROW;
    #pragma unroll
    for (int j = lane; j < TS; j += 32)
        Gr[j] = __float2half(fmaf(raw[r][lab[j]], LOG2E, -lse2));
    if (lane == 0)
        Gr[256] = __float2half(fmaf(raw[r][0], LOG2E, -lse2));
}

// ---------------------------------------------------------------------------
// Main kernel: wavefront-blocked alpha recursion, 1 barrier per 8 timesteps.
// Warp w, lane j: pair p = 24w + j - 8 (states 2p, 2p+1). j<8 = ghost lanes.
// ---------------------------------------------------------------------------
__global__ void __launch_bounds__(NTH, 1) ctc_kernel(
    const int* __restrict__ tgt32,
    const int* __restrict__ tmask,
    float*     __restrict__ out)
{
    __shared__ __align__(16) __half ring[RCH][8 * GROW];   // 21120 B
    __shared__ float bnd[2][NW][GH][2];  // [parity][warp][slot][aE,aO]
    __shared__ float fin[514];
    __shared__ int   lab[TS];
    __shared__ int   tlen_sh;

    const int tid = threadIdx.x, lane = tid & 31, w = tid >> 5;
    const int b = blockIdx.x;
    const int p = OWN * w + lane - GH;   // pair index

    const bool is64 = (tgt32[1] == 0);
    const int  stride = is64 ? 2 : 1;
    if (tid < TS) lab[tid] = tgt32[((size_t)b * TS + tid) * stride];
    if (tid < 2 * NW * GH * 2) ((float*)bnd)[tid] = NEGF;
    if (w == 0) {
        int s = 0;
        #pragma unroll
        for (int k = lane; k < TS; k += 32) s += tmask[b * TS + k];
        #pragma unroll
        for (int o = 16; o; o >>= 1) s += __shfl_xor_sync(0xffffffffu, s, o);
        if (lane == 0) tlen_sh = s;
    }
    __syncthreads();

    const bool hasLab = (p >= 0) && (p < 256);
    const bool skip   = hasLab && (p > 0) && (lab[p] != lab[p - 1]);

    const __half* Gb = g_gt + ((size_t)b * TT) * GROW;

    auto issue_chunk = [&](int c) {
        if (c < NCHK) {
            unsigned sa = (unsigned)__cvta_generic_to_shared(ring[c % RCH]);
            const __half* src = Gb + (size_t)c * (8 * GROW);
            if (tid < 264)
                asm volatile("cp.async.ca.shared.global [%0], [%1], 16;"
                             :: "r"(sa + tid * 16), "l"(src + tid * 8));
        }
        asm volatile("cp.async.commit_group;");
    };

    issue_chunk(0); issue_chunk(1); issue_chunk(2); issue_chunk(3);

    // virtual t=-1 seed: aE(p=0)=0 makes the uniform loop emit alpha0 at t=0
    float aE = (p == 0) ? 0.0f : NEGF;
    float aO = NEGF;
    int   pb = 0;

    for (int r = 0; r < TT / 8; ++r) {
        asm volatile("cp.async.wait_group 3;");     // chunk r resident
        __syncthreads();
        issue_chunk(r + 4);

        // ghost refresh from left warp's last-round publish
        if (lane < GH && w > 0) {
            aE = bnd[pb][w - 1][lane][0];
            aO = bnd[pb][w - 1][lane][1];
        }

        const __half* Rc = ring[r % RCH];
        float lpv[8], lpB[8];
        #pragma unroll
        for (int k = 0; k < 8; ++k) {
            const __half* R = Rc + k * GROW;
            lpv[k] = hasLab ? __half2float(R[p]) : NEGF;
            lpB[k] = __half2float(R[256]);
        }

        #pragma unroll
        for (int k = 0; k < 8; ++k) {
            float lo = __shfl_up_sync(0xffffffffu, aO, 1);
            if (lane == 0) lo = NEGF;
            float nE = lse2f_(aE, lo) + lpB[k];                   // state 2p
            float nO = lse3f_(aO, aE, skip ? lo : NEGF) + lpv[k]; // state 2p+1
            aE = nE; aO = nO;
        }

        if (lane >= 32 - GH) {       // publish top GH owned pairs for warp w+1
            bnd[pb ^ 1][w][lane - (32 - GH)][0] = aE;
            bnd[pb ^ 1][w][lane - (32 - GH)][1] = aO;
        }
        pb ^= 1;
    }

    if (lane >= GH && p <= 256) {    // owned, in-trellis
        fin[2 * p] = aE;
        if (p < 256) fin[2 * p + 1] = aO;
    }
    __syncthreads();

    if (tid == 0) {
        int len = tlen_sh;
        float loss = 0.0f;
        if (len >= 1 && len <= TS) {
            float la = lse2f_(fin[2 * len], fin[2 * len - 1]);
            float l  = -la * LN2;
            if (isfinite(l) && l < 1e29f)
                loss = l / ((float)len * (float)TB);
        }
        atomicAdd(out, loss);
    }
}

// ---------------------------------------------------------------------------
extern "C" void kernel_launch(void* const* d_in, const int* in_sizes, int n_in,
                              void* d_out, int out_size) {
    const float* x     = (const float*)d_in[0];   // predictions [B,T,C] f32
    const int*   tgt   = (const int*)  d_in[1];   // targets (int32 or int64 words)
    const int*   tmask = (const int*)  d_in[3];   // targets_mask [B,S] i32
    float* out = (float*)d_out;

    dim3 ggrid(TT / 8, TB);
    gather_kernel<<<ggrid, 256>>>(x, tgt, out);
    ctc_kernel<<<TB, NTH>>>(tgt, tmask, out);
}